// round 8
// baseline (speedup 1.0000x reference)
#include <cuda_runtime.h>
#include <cuda_bf16.h>
#include <cstdint>
#include <math.h>

// ---------------------------------------------------------------------------
// Problem constants
// ---------------------------------------------------------------------------
#define B_ROWS   8192
#define M_EXP    10
#define N_TASK   100
#define F_CONN   10
#define T_OUT    10
#define K_IN     4096
#define H1_DIM   120

// E1 packing geometry
#define E1_BK        32
#define E1_NC        (K_IN / E1_BK)     // 128 chunks
#define PK_COLS      40                 // 32 data bf16 + 8 pad -> 80B rows

// ---------------------------------------------------------------------------
// Scratch (device globals)
// ---------------------------------------------------------------------------
__device__ float g_EO[(size_t)M_EXP * B_ROWS * 10];    // expert out [M,B,F]

// chunk-major packed hi/lo for E1 bulk loads
__device__ __nv_bfloat16 g_xph[(size_t)E1_NC * B_ROWS * PK_COLS];
__device__ __nv_bfloat16 g_xpl[(size_t)E1_NC * B_ROWS * PK_COLS];
__device__ __nv_bfloat16 g_wph[(size_t)M_EXP * E1_NC * 128 * PK_COLS];
__device__ __nv_bfloat16 g_wpl[(size_t)M_EXP * E1_NC * 128 * PK_COLS];

// packed W2 for E2/T2: [batch][chunk 4][96][40]  (hi, lo)
__device__ __nv_bfloat16 g_w2h[(size_t)M_EXP * 4 * 96 * PK_COLS];
__device__ __nv_bfloat16 g_w2l[(size_t)M_EXP * 4 * 96 * PK_COLS];
__device__ __nv_bfloat16 g_tw2h[(size_t)N_TASK * 4 * 96 * PK_COLS];
__device__ __nv_bfloat16 g_tw2l[(size_t)N_TASK * 4 * 96 * PK_COLS];

// ---------------------------------------------------------------------------
// f32x2 helpers
// ---------------------------------------------------------------------------
__device__ __forceinline__ void fma2(unsigned long long& d,
                                     unsigned long long a,
                                     unsigned long long b) {
    asm("fma.rn.f32x2 %0, %1, %2, %0;" : "+l"(d) : "l"(a), "l"(b));
}
__device__ __forceinline__ unsigned long long dup2(float x) {
    unsigned long long r;
    unsigned int xi = __float_as_uint(x);
    asm("mov.b64 %0, {%1, %1};" : "=l"(r) : "r"(xi));
    return r;
}
__device__ __forceinline__ unsigned long long pack2(float lo, float hi) {
    unsigned long long r;
    asm("mov.b64 %0, {%1, %2};" : "=l"(r)
        : "r"(__float_as_uint(lo)), "r"(__float_as_uint(hi)));
    return r;
}
__device__ __forceinline__ void unpack2(unsigned long long v, float& lo, float& hi) {
    unsigned int a, b;
    asm("mov.b64 {%0, %1}, %2;" : "=r"(a), "=r"(b) : "l"(v));
    lo = __uint_as_float(a);
    hi = __uint_as_float(b);
}

// ---------------------------------------------------------------------------
// PTX helpers (<= sm_90 baseline; legal at virtual arch compute_103)
// ---------------------------------------------------------------------------
__device__ __forceinline__ uint32_t smem_u32(const void* p) {
    uint32_t a;
    asm("{ .reg .u64 t; cvta.to.shared.u64 t, %1; cvt.u32.u64 %0, t; }"
        : "=r"(a) : "l"(p));
    return a;
}
__device__ __forceinline__ void mbar_init(uint32_t mb, uint32_t cnt) {
    asm volatile("mbarrier.init.shared.b64 [%0], %1;" :: "r"(mb), "r"(cnt) : "memory");
}
__device__ __forceinline__ void mbar_expect_tx(uint32_t mb, uint32_t bytes) {
    asm volatile("mbarrier.arrive.expect_tx.shared.b64 _, [%0], %1;"
                 :: "r"(mb), "r"(bytes) : "memory");
}
__device__ __forceinline__ void mbar_wait(uint32_t mb, uint32_t parity) {
    asm volatile("{\n\t.reg .pred P;\n"
                 "W%=:\n\t"
                 "mbarrier.try_wait.parity.acquire.cta.shared::cta.b64 P, [%0], %1, 0x989680;\n\t"
                 "@P bra D%=;\n\t"
                 "bra W%=;\n"
                 "D%=:\n\t}"
                 :: "r"(mb), "r"(parity) : "memory");
}
__device__ __forceinline__ void bulk_g2s(uint32_t dst, const void* src,
                                         uint32_t bytes, uint32_t mb) {
    asm volatile("cp.async.bulk.shared::cta.global.mbarrier::complete_tx::bytes "
                 "[%0], [%1], %2, [%3];"
                 :: "r"(dst), "l"(src), "r"(bytes), "r"(mb) : "memory");
}
__device__ __forceinline__ void ldsm_x4(uint32_t& r0, uint32_t& r1,
                                        uint32_t& r2, uint32_t& r3, uint32_t a) {
    asm volatile("ldmatrix.sync.aligned.m8n8.x4.shared.b16 {%0,%1,%2,%3}, [%4];"
                 : "=r"(r0), "=r"(r1), "=r"(r2), "=r"(r3) : "r"(a));
}
__device__ __forceinline__ void mma_bf16(float& c0, float& c1, float& c2, float& c3,
                                         uint32_t a0, uint32_t a1, uint32_t a2, uint32_t a3,
                                         uint32_t b0, uint32_t b1) {
    asm volatile("mma.sync.aligned.m16n8k16.row.col.f32.bf16.bf16.f32 "
                 "{%0,%1,%2,%3},{%4,%5,%6,%7},{%8,%9},{%0,%1,%2,%3};"
                 : "+f"(c0), "+f"(c1), "+f"(c2), "+f"(c3)
                 : "r"(a0), "r"(a1), "r"(a2), "r"(a3), "r"(b0), "r"(b1));
}

// ---------------------------------------------------------------------------
// Packing kernels
// ---------------------------------------------------------------------------
__global__ void pack_x_kernel(const float* __restrict__ x,
                              __nv_bfloat16* __restrict__ xph,
                              __nv_bfloat16* __restrict__ xpl)
{
    size_t i = (size_t)blockIdx.x * blockDim.x + threadIdx.x;
    const size_t total = (size_t)E1_NC * B_ROWS * PK_COLS;
    if (i >= total) return;
    int col = (int)(i % PK_COLS);
    int row = (int)((i / PK_COLS) % B_ROWS);
    int c   = (int)(i / ((size_t)PK_COLS * B_ROWS));
    float v = 0.f;
    if (col < E1_BK) v = x[(size_t)row * K_IN + c * E1_BK + col];
    __nv_bfloat16 h = __float2bfloat16(v);
    xph[i] = h;
    xpl[i] = __float2bfloat16(v - __bfloat162float(h));
}

__global__ void pack_w_kernel(const float* __restrict__ w,
                              __nv_bfloat16* __restrict__ wph,
                              __nv_bfloat16* __restrict__ wpl)
{
    size_t i = (size_t)blockIdx.x * blockDim.x + threadIdx.x;
    const size_t total = (size_t)M_EXP * E1_NC * 128 * PK_COLS;
    if (i >= total) return;
    int col = (int)(i % PK_COLS);
    int n   = (int)((i / PK_COLS) % 128);
    int c   = (int)((i / ((size_t)PK_COLS * 128)) % E1_NC);
    int m   = (int)(i / ((size_t)PK_COLS * 128 * E1_NC));
    float v = 0.f;
    if (col < E1_BK && n < H1_DIM)
        v = w[((size_t)m * K_IN + c * E1_BK + col) * H1_DIM + n];
    __nv_bfloat16 h = __float2bfloat16(v);
    wph[i] = h;
    wpl[i] = __float2bfloat16(v - __bfloat162float(h));
}

// w [b][Kreal][Nreal] -> [b][4][96][40] transposed chunk-major zero-padded
__global__ void pack_w2_kernel(const float* __restrict__ w, int batchN,
                               int Kreal, int Nreal,
                               __nv_bfloat16* __restrict__ wh,
                               __nv_bfloat16* __restrict__ wl)
{
    size_t i = (size_t)blockIdx.x * blockDim.x + threadIdx.x;
    size_t total = (size_t)batchN * 4 * 96 * PK_COLS;
    if (i >= total) return;
    int col = (int)(i % PK_COLS);
    int n   = (int)((i / PK_COLS) % 96);
    int c   = (int)((i / (PK_COLS * 96)) % 4);
    int b   = (int)(i / ((size_t)PK_COLS * 96 * 4));
    int k   = c * 32 + col;
    float v = (col < 32 && k < Kreal && n < Nreal)
              ? w[((size_t)b * Kreal + k) * Nreal + n] : 0.f;
    __nv_bfloat16 h = __float2bfloat16(v);
    wh[i] = h;
    wl[i] = __float2bfloat16(v - __bfloat162float(h));
}

// ---------------------------------------------------------------------------
// expert_kernel: E1 (3-stage bulk pipeline) + E2 (3-pass HMMA) + E3 epilogue
//   EO[m][r][10] = relu(x@eW1+eb1) @ eW2 + eb2 -> relu -> @ eW3 + eb3
// grid = (M_EXP, 64), 256 threads.
// ---------------------------------------------------------------------------
#define RS           80           // smem bf16 tile row stride bytes
#define E1_STAGE     40960        // per-stage (Ah|Al|Bh|Bl 10240 each)
#define XA_H         0            // within stage
#define XA_L         10240
#define XB_H         20480
#define XB_L         30720
// layout: stage0 @0, stage1 @40960, stage2 @81920
// E2 phase reuse: Ah @0, Al @40960 ([chunk4][128][40]); w3s @81920
#define E2B_H        122880       // [4][96][40] = 30720
#define E2B_L        153600
#define MIDS_OFF     122880       // overlay B after MMA (46080 <= 61440)
#define MSTR         90
#define W3S_OFF      81920
#define EK_MBAR      184320
#define EK_SMEM      184352

__global__ __launch_bounds__(256)
void expert_kernel(const __nv_bfloat16* __restrict__ xph,
                   const __nv_bfloat16* __restrict__ xpl,
                   const __nv_bfloat16* __restrict__ wph,
                   const __nv_bfloat16* __restrict__ wpl,
                   const float* __restrict__ eb1,
                   const __nv_bfloat16* __restrict__ w2h,
                   const __nv_bfloat16* __restrict__ w2l,
                   const float* __restrict__ eb2,
                   const float* __restrict__ eW3,
                   const float* __restrict__ eb3,
                   float* __restrict__ EO)
{
    extern __shared__ char smem[];
    const uint32_t sb = smem_u32(smem);
    const int t    = threadIdx.x;
    const int lane = t & 31;
    const int wid  = t >> 5;
    const int wm   = wid >> 1;
    const int wn   = wid & 1;

    const int m     = blockIdx.x;
    const int tileY = blockIdx.y;
    const int r0    = tileY * 128;

    const uint32_t mb = sb + EK_MBAR;   // mb+0,8,16: E1 stages; mb+24: E2 B

    if (t == 0) {
        mbar_init(mb + 0, 1);
        mbar_init(mb + 8, 1);
        mbar_init(mb + 16, 1);
        mbar_init(mb + 24, 1);
    }
    __syncthreads();

    // issue E2 B load early (overlaps all of E1)
    if (t == 0) {
        mbar_expect_tx(mb + 24, 2 * 30720);
        bulk_g2s(sb + E2B_H, w2h + (size_t)m * 4 * 96 * PK_COLS, 30720, mb + 24);
        bulk_g2s(sb + E2B_L, w2l + (size_t)m * 4 * 96 * PK_COLS, 30720, mb + 24);
    }

    // ---------------- E1 ----------------
    float acc[2][8][4];
    #pragma unroll
    for (int i = 0; i < 2; i++)
        #pragma unroll
        for (int j = 0; j < 8; j++)
            #pragma unroll
            for (int q = 0; q < 4; q++)
                acc[i][j][q] = 0.f;

    const uint32_t a_base = (uint32_t)((wm * 32 + (lane & 15)) * RS + (lane >> 4) * 16);
    const uint32_t b_base = (uint32_t)((wn * 64 + (lane & 15)) * RS + (lane >> 4) * 16);

    uint32_t ph[3] = {0u, 0u, 0u};

    // issue helper inline (t==0 only)
    auto issue = [&](int c, int s) {
        mbar_expect_tx(mb + 8 * s, 4 * 10240);
        const uint32_t stg = sb + s * E1_STAGE;
        const size_t aoff = ((size_t)c * B_ROWS + (size_t)tileY * 128) * PK_COLS;
        const size_t boff = ((size_t)m * E1_NC + c) * 128 * PK_COLS;
        bulk_g2s(stg + XA_H, xph + aoff, 10240, mb + 8 * s);
        bulk_g2s(stg + XA_L, xpl + aoff, 10240, mb + 8 * s);
        bulk_g2s(stg + XB_H, wph + boff, 10240, mb + 8 * s);
        bulk_g2s(stg + XB_L, wpl + boff, 10240, mb + 8 * s);
    };

    if (t == 0) { issue(0, 0); issue(1, 1); }

    for (int c = 0; c < E1_NC; c++) {
        const int s = c % 3;
        if (c + 2 < E1_NC && t == 0) issue(c + 2, (c + 2) % 3);
        mbar_wait(mb + 8 * s, ph[s]);
        ph[s] ^= 1u;

        const uint32_t stg = sb + s * E1_STAGE;
        #pragma unroll
        for (int ks = 0; ks < 2; ks++) {
            const uint32_t ko = ks * 32;
            uint32_t ah[2][4], al[2][4];
            #pragma unroll
            for (int mt = 0; mt < 2; mt++) {
                uint32_t ad = stg + a_base + mt * (16 * RS) + ko;
                ldsm_x4(ah[mt][0], ah[mt][1], ah[mt][2], ah[mt][3], ad + XA_H);
                ldsm_x4(al[mt][0], al[mt][1], al[mt][2], al[mt][3], ad + XA_L);
            }
            uint32_t bh[4][4], bl[4][4];
            #pragma unroll
            for (int g = 0; g < 4; g++) {
                uint32_t bd = stg + b_base + g * (16 * RS) + ko;
                ldsm_x4(bh[g][0], bh[g][1], bh[g][2], bh[g][3], bd + XB_H);
                ldsm_x4(bl[g][0], bl[g][1], bl[g][2], bl[g][3], bd + XB_L);
            }
            #pragma unroll
            for (int mt = 0; mt < 2; mt++) {
                #pragma unroll
                for (int nt = 0; nt < 8; nt++) {
                    const int g = nt >> 1, p = (nt & 1);
                    float* cc = acc[mt][nt];
                    mma_bf16(cc[0], cc[1], cc[2], cc[3],
                             ah[mt][0], ah[mt][1], ah[mt][2], ah[mt][3],
                             bh[g][p], bh[g][p + 2]);
                    mma_bf16(cc[0], cc[1], cc[2], cc[3],
                             ah[mt][0], ah[mt][1], ah[mt][2], ah[mt][3],
                             bl[g][p], bl[g][p + 2]);
                    mma_bf16(cc[0], cc[1], cc[2], cc[3],
                             al[mt][0], al[mt][1], al[mt][2], al[mt][3],
                             bh[g][p], bh[g][p + 2]);
                }
            }
        }
        __syncthreads();
    }

    // ---------------- write H1 tile (relu+bias, split hi/lo) to smem ----------------
    {
        const float* bias = eb1 + (size_t)m * H1_DIM;
        const int rl = wm * 32 + (lane >> 2);
        const int cb = wn * 64 + (lane & 3) * 2;
        #pragma unroll
        for (int mt = 0; mt < 2; mt++) {
            #pragma unroll
            for (int half = 0; half < 2; half++) {
                const int r = rl + mt * 16 + half * 8;
                #pragma unroll
                for (int nt = 0; nt < 8; nt++) {
                    const int ccol = cb + nt * 8;
                    if (ccol < H1_DIM) {
                        float v0 = fmaxf(acc[mt][nt][half * 2 + 0] + bias[ccol], 0.f);
                        float v1 = fmaxf(acc[mt][nt][half * 2 + 1] + bias[ccol + 1], 0.f);
                        __nv_bfloat16 h0 = __float2bfloat16(v0);
                        __nv_bfloat16 h1 = __float2bfloat16(v1);
                        __nv_bfloat162 hh; hh.x = h0; hh.y = h1;
                        __nv_bfloat162 ll;
                        ll.x = __float2bfloat16(v0 - __bfloat162float(h0));
                        ll.y = __float2bfloat16(v1 - __bfloat162float(h1));
                        uint32_t off = (ccol >> 5) * 10240 + r * RS + (ccol & 31) * 2;
                        *reinterpret_cast<__nv_bfloat162*>(smem + 0     + off) = hh;
                        *reinterpret_cast<__nv_bfloat162*>(smem + 40960 + off) = ll;
                    }
                }
            }
        }
        // zero A pad: chunk3 cols 24..31 (k = 120..127), both matrices
        if (t < 128) {
            uint32_t off = 3 * 10240 + t * RS + 48;
            *reinterpret_cast<uint4*>(smem + 0     + off) = make_uint4(0u,0u,0u,0u);
            *reinterpret_cast<uint4*>(smem + 40960 + off) = make_uint4(0u,0u,0u,0u);
        }
        // load eW3 into smem
        float* w3s = reinterpret_cast<float*>(smem + W3S_OFF);
        const float* w3g = eW3 + (size_t)m * (84 * T_OUT);
        for (int i = t; i < 84 * T_OUT; i += 256) w3s[i] = w3g[i];
    }
    mbar_wait(mb + 24, 0);
    __syncthreads();

    // ---------------- E2 MMA ----------------
    float acc2[2][6][4];
    #pragma unroll
    for (int i = 0; i < 2; i++)
        #pragma unroll
        for (int j = 0; j < 6; j++)
            #pragma unroll
            for (int q = 0; q < 4; q++)
                acc2[i][j][q] = 0.f;

    const uint32_t b2_base = (uint32_t)((wn * 48 + (lane & 15)) * RS + (lane >> 4) * 16);
    #pragma unroll
    for (int ch = 0; ch < 4; ch++) {
        #pragma unroll
        for (int ks = 0; ks < 2; ks++) {
            const uint32_t ko = ks * 32;
            uint32_t ah[2][4], al[2][4];
            #pragma unroll
            for (int mt = 0; mt < 2; mt++) {
                uint32_t ad = sb + ch * 10240 + a_base + mt * (16 * RS) + ko;
                ldsm_x4(ah[mt][0], ah[mt][1], ah[mt][2], ah[mt][3], ad + 0);
                ldsm_x4(al[mt][0], al[mt][1], al[mt][2], al[mt][3], ad + 40960);
            }
            uint32_t bh[3][4], bl[3][4];
            #pragma unroll
            for (int g = 0; g < 3; g++) {
                uint32_t bd = sb + ch * 7680 + b2_base + g * (16 * RS) + ko;
                ldsm_x4(bh[g][0], bh[g][1], bh[g][2], bh[g][3], bd + E2B_H);
                ldsm_x4(bl[g][0], bl[g][1], bl[g][2], bl[g][3], bd + E2B_L);
            }
            #pragma unroll
            for (int mt = 0; mt < 2; mt++) {
                #pragma unroll
                for (int nt = 0; nt < 6; nt++) {
                    const int g = nt >> 1, p = (nt & 1);
                    float* cc = acc2[mt][nt];
                    mma_bf16(cc[0], cc[1], cc[2], cc[3],
                             ah[mt][0], ah[mt][1], ah[mt][2], ah[mt][3],
                             bh[g][p], bh[g][p + 2]);
                    mma_bf16(cc[0], cc[1], cc[2], cc[3],
                             ah[mt][0], ah[mt][1], ah[mt][2], ah[mt][3],
                             bl[g][p], bl[g][p + 2]);
                    mma_bf16(cc[0], cc[1], cc[2], cc[3],
                             al[mt][0], al[mt][1], al[mt][2], al[mt][3],
                             bh[g][p], bh[g][p + 2]);
                }
            }
        }
    }
    __syncthreads();

    // ---------------- E3 epilogue ----------------
    float* mids = reinterpret_cast<float*>(smem + MIDS_OFF);
    float* w3s  = reinterpret_cast<float*>(smem + W3S_OFF);
    {
        const float* b2 = eb2 + (size_t)m * 84;
        const int rl = wm * 32 + (lane >> 2);
        const int cb = wn * 48 + (lane & 3) * 2;
        #pragma unroll
        for (int mt = 0; mt < 2; mt++) {
            #pragma unroll
            for (int half = 0; half < 2; half++) {
                const int r = rl + mt * 16 + half * 8;
                float* row = mids + r * MSTR;
                #pragma unroll
                for (int nt = 0; nt < 6; nt++) {
                    const int ccol = cb + nt * 8;
                    if (ccol < 84) {
                        float2 v;
                        v.x = fmaxf(acc2[mt][nt][half * 2 + 0] + b2[ccol], 0.f);
                        v.y = fmaxf(acc2[mt][nt][half * 2 + 1] + b2[ccol + 1], 0.f);
                        *reinterpret_cast<float2*>(row + ccol) = v;
                    }
                }
            }
        }
    }
    __syncthreads();
    {
        const int r  = t >> 1;
        const int c0 = (t & 1) * 5;
        const float* b3 = eb3 + (size_t)m * T_OUT;
        float a[5];
        #pragma unroll
        for (int j = 0; j < 5; j++) a[j] = b3[c0 + j];
        const float* row = mids + r * MSTR;
        for (int k = 0; k < 84; k++) {
            float tv = row[k];
            #pragma unroll
            for (int j = 0; j < 5; j++)
                a[j] = fmaf(tv, w3s[k * T_OUT + c0 + j], a[j]);
        }
        float* dst = EO + ((size_t)m * B_ROWS + r0 + r) * T_OUT + c0;
        #pragma unroll
        for (int j = 0; j < 5; j++) dst[j] = a[j];
    }
}

// ---------------------------------------------------------------------------
// task_kernel: gate + T1 (FFMA2) + T2 (3-pass HMMA) + T3 epilogue
//   out[n][r][10]
// grid = (N_TASK, 64), 256 threads.
// ---------------------------------------------------------------------------
#define TK_AH      0              // [4][128][40] = 40960
#define TK_AL      40960
#define TK_BH      81920          // [4][96][40] = 30720
#define TK_BL      112640
#define TK_GS      143360         // 128*10 fp32 = 5120
#define TK_W1      148480         // 10*120 fp32 = 4800
#define TK_W3      153280         // 84*10 fp32 = 3360
#define TK_MBAR    156672
#define TK_MIDS    81920          // overlay B after MMA (46080 <= 61440)
#define TK_SMEM    156704

__global__ __launch_bounds__(256)
void task_kernel(const float* __restrict__ EO,
                 const float* __restrict__ gw,
                 const int*   __restrict__ gm,
                 const float* __restrict__ tW1,
                 const float* __restrict__ tb1,
                 const __nv_bfloat16* __restrict__ tw2h,
                 const __nv_bfloat16* __restrict__ tw2l,
                 const float* __restrict__ tb2,
                 const float* __restrict__ tW3,
                 const float* __restrict__ tb3,
                 float* __restrict__ Out)
{
    extern __shared__ char smem[];
    const uint32_t sb = smem_u32(smem);
    const int t    = threadIdx.x;
    const int lane = t & 31;
    const int wid  = t >> 5;
    const int wm   = wid >> 1;
    const int wn   = wid & 1;

    const int n  = blockIdx.x;
    const int r0 = blockIdx.y * 128;

    const uint32_t mb = sb + TK_MBAR;
    if (t == 0) mbar_init(mb, 1);
    __syncthreads();
    if (t == 0) {
        mbar_expect_tx(mb, 2 * 30720);
        bulk_g2s(sb + TK_BH, tw2h + (size_t)n * 4 * 96 * PK_COLS, 30720, mb);
        bulk_g2s(sb + TK_BL, tw2l + (size_t)n * 4 * 96 * PK_COLS, 30720, mb);
    }

    float* Gs  = reinterpret_cast<float*>(smem + TK_GS);
    float* W1s = reinterpret_cast<float*>(smem + TK_W1);
    float* w3s = reinterpret_cast<float*>(smem + TK_W3);

    // gate weights
    float w[M_EXP];
    #pragma unroll
    for (int m = 0; m < M_EXP; m++)
        w[m] = gw[m * N_TASK + n] * (float)gm[m * N_TASK + n];

    // gate combine
    for (int i = t; i < 128 * F_CONN; i += 256) {
        float acc = 0.f;
        #pragma unroll
        for (int m = 0; m < M_EXP; m++)
            acc = fmaf(w[m], EO[((size_t)m * B_ROWS + r0) * F_CONN + i], acc);
        Gs[i] = acc;
    }
    for (int i = t; i < F_CONN * 120; i += 256)
        W1s[i] = tW1[(size_t)n * F_CONN * 120 + i];
    for (int i = t; i < 84 * T_OUT; i += 256)
        w3s[i] = tW3[(size_t)n * 84 * T_OUT + i];
    __syncthreads();

    // T1: thread = (row r, 60-col half), FFMA2; write relu'd hi/lo to A tile
    {
        const int r  = t >> 1;
        const int h0 = (t & 1) * 60;
        float g[F_CONN];
        #pragma unroll
        for (int f = 0; f < F_CONN; f++) g[f] = Gs[r * F_CONN + f];

        unsigned long long a2[30];
        const float* b1 = tb1 + (size_t)n * 120 + h0;
        #pragma unroll
        for (int j = 0; j < 30; j++) a2[j] = pack2(b1[2 * j], b1[2 * j + 1]);
        #pragma unroll
        for (int f = 0; f < F_CONN; f++) {
            unsigned long long gv = dup2(g[f]);
            const unsigned long long* wrow =
                reinterpret_cast<const unsigned long long*>(W1s + f * 120 + h0);
            #pragma unroll
            for (int j = 0; j < 30; j++) fma2(a2[j], gv, wrow[j]);
        }
        #pragma unroll
        for (int j = 0; j < 30; j++) {
            float v0, v1;
            unpack2(a2[j], v0, v1);
            v0 = fmaxf(v0, 0.f);
            v1 = fmaxf(v1, 0.f);
            __nv_bfloat16 h0b = __float2bfloat16(v0);
            __nv_bfloat16 h1b = __float2bfloat16(v1);
            __nv_bfloat162 hh; hh.x = h0b; hh.y = h1b;
            __nv_bfloat162 ll;
            ll.x = __float2bfloat16(v0 - __bfloat162float(h0b));
            ll.y = __float2bfloat16(v1 - __bfloat162float(h1b));
            const int c = h0 + 2 * j;
            uint32_t off = (c >> 5) * 10240 + r * RS + (c & 31) * 2;
            *reinterpret_cast<__nv_bfloat162*>(smem + TK_AH + off) = hh;
            *reinterpret_cast<__nv_bfloat162*>(smem + TK_AL + off) = ll;
        }
        // zero A pad chunk3 cols 24..31 (k=120..127)
        if (t & 1) {
            uint32_t off = 3 * 10240 + r * RS + 48;
            *reinterpret_cast<uint4*>(smem + TK_AH + off) = make_uint4(0u,0u,0u,0u);
            *reinterpret_cast<uint4*>(smem + TK_AL + off) = make_uint4(0u,0u,0u,0u);
        }
    }
    mbar_wait(mb, 0);
    __syncthreads();

    // T2 MMA
    float acc2[2][6][4];
    #pragma unroll
    for (int i = 0; i < 2; i++)
        #pragma unroll
        for (int j = 0; j < 6; j++)
            #pragma unroll
            for (int q = 0; q < 4; q++)
                acc2[i][j][q] = 0.f;

    const uint32_t a_base  = (uint32_t)((wm * 32 + (lane & 15)) * RS + (lane >> 4) * 16);
    const uint32_t b2_base = (uint32_t)((wn * 48 + (lane & 15)) * RS + (lane >> 4) * 16);
    #pragma unroll
    for (int ch = 0; ch < 4; ch++) {
        #pragma unroll
        for (int ks = 0; ks < 2; ks++) {
            const uint32_t ko = ks * 32;
            uint32_t ah[2][4], al[2][4];
            #pragma unroll
            for (int mt = 0; mt < 2; mt++) {
                uint32_t ad = sb + ch * 10240 + a_base + mt * (16 * RS) + ko;
                ldsm_x4(ah[mt][0], ah[mt][1], ah[mt][2], ah[mt][3], ad + TK_AH);
                ldsm_x4(al[mt][0], al[mt][1], al[mt][2], al[mt][3], ad + TK_AL);
            }
            uint32_t bh[3][4], bl[3][4];
            #pragma unroll
            for (int g = 0; g < 3; g++) {
                uint32_t bd = sb + ch * 7680 + b2_base + g * (16 * RS) + ko;
                ldsm_x4(bh[g][0], bh[g][1], bh[g][2], bh[g][3], bd + TK_BH);
                ldsm_x4(bl[g][0], bl[g][1], bl[g][2], bl[g][3], bd + TK_BL);
            }
            #pragma unroll
            for (int mt = 0; mt < 2; mt++) {
                #pragma unroll
                for (int nt = 0; nt < 6; nt++) {
                    const int g = nt >> 1, p = (nt & 1);
                    float* cc = acc2[mt][nt];
                    mma_bf16(cc[0], cc[1], cc[2], cc[3],
                             ah[mt][0], ah[mt][1], ah[mt][2], ah[mt][3],
                             bh[g][p], bh[g][p + 2]);
                    mma_bf16(cc[0], cc[1], cc[2], cc[3],
                             ah[mt][0], ah[mt][1], ah[mt][2], ah[mt][3],
                             bl[g][p], bl[g][p + 2]);
                    mma_bf16(cc[0], cc[1], cc[2], cc[3],
                             al[mt][0], al[mt][1], al[mt][2], al[mt][3],
                             bh[g][p], bh[g][p + 2]);
                }
            }
        }
    }
    __syncthreads();

    // T3 epilogue
    float* mids = reinterpret_cast<float*>(smem + TK_MIDS);
    {
        const float* b2 = tb2 + (size_t)n * 84;
        const int rl = wm * 32 + (lane >> 2);
        const int cb = wn * 48 + (lane & 3) * 2;
        #pragma unroll
        for (int mt = 0; mt < 2; mt++) {
            #pragma unroll
            for (int half = 0; half < 2; half++) {
                const int r = rl + mt * 16 + half * 8;
                float* row = mids + r * MSTR;
                #pragma unroll
                for (int nt = 0; nt < 6; nt++) {
                    const int ccol = cb + nt * 8;
                    if (ccol < 84) {
                        float2 v;
                        v.x = fmaxf(acc2[mt][nt][half * 2 + 0] + b2[ccol], 0.f);
                        v.y = fmaxf(acc2[mt][nt][half * 2 + 1] + b2[ccol + 1], 0.f);
                        *reinterpret_cast<float2*>(row + ccol) = v;
                    }
                }
            }
        }
    }
    __syncthreads();
    {
        const int r  = t >> 1;
        const int c0 = (t & 1) * 5;
        const float* b3 = tb3 + (size_t)n * T_OUT;
        float a[5];
        #pragma unroll
        for (int j = 0; j < 5; j++) a[j] = b3[c0 + j];
        const float* row = mids + r * MSTR;
        for (int k = 0; k < 84; k++) {
            float tv = row[k];
            #pragma unroll
            for (int j = 0; j < 5; j++)
                a[j] = fmaf(tv, w3s[k * T_OUT + c0 + j], a[j]);
        }
        float* dst = Out + ((size_t)n * B_ROWS + r0 + r) * T_OUT + c0;
        #pragma unroll
        for (int j = 0; j < 5; j++) dst[j] = a[j];
    }
}

// ---------------------------------------------------------------------------
// logits_loss[n] = sum_m log_sigmoid(gate_logits[m][n])
// ---------------------------------------------------------------------------
__global__ void logits_kernel(const float* __restrict__ gl, float* __restrict__ out)
{
    int n = blockIdx.x * blockDim.x + threadIdx.x;
    if (n >= N_TASK) return;
    float acc = 0.f;
    #pragma unroll
    for (int m = 0; m < M_EXP; m++) {
        float v = gl[m * N_TASK + n];
        float ls = (v > 0.f) ? (-log1pf(expf(-v))) : (v - log1pf(expf(v)));
        acc += ls;
    }
    out[n] = acc;
}

// ---------------------------------------------------------------------------
// kernel_launch
// ---------------------------------------------------------------------------
extern "C" void kernel_launch(void* const* d_in, const int* in_sizes, int n_in,
                              void* d_out, int out_size)
{
    const float* x   = (const float*)d_in[0];
    const float* eW1 = (const float*)d_in[2];
    const float* eb1 = (const float*)d_in[3];
    const float* eW2 = (const float*)d_in[4];
    const float* eb2 = (const float*)d_in[5];
    const float* eW3 = (const float*)d_in[6];
    const float* eb3 = (const float*)d_in[7];
    const float* gw  = (const float*)d_in[8];
    const float* gl  = (const float*)d_in[9];
    const int*   gm  = (const int*)  d_in[10];
    const float* tW1 = (const float*)d_in[11];
    const float* tb1 = (const float*)d_in[12];
    const float* tW2 = (const float*)d_in[13];
    const float* tb2 = (const float*)d_in[14];
    const float* tW3 = (const float*)d_in[15];
    const float* tb3 = (const float*)d_in[16];
    float* out = (float*)d_out;

    float *EO;
    __nv_bfloat16 *xph, *xpl, *wph, *wpl, *w2h, *w2l, *tw2h, *tw2l;
    cudaGetSymbolAddress((void**)&EO,  g_EO);
    cudaGetSymbolAddress((void**)&xph, g_xph);
    cudaGetSymbolAddress((void**)&xpl, g_xpl);
    cudaGetSymbolAddress((void**)&wph, g_wph);
    cudaGetSymbolAddress((void**)&wpl, g_wpl);
    cudaGetSymbolAddress((void**)&w2h, g_w2h);
    cudaGetSymbolAddress((void**)&w2l, g_w2l);
    cudaGetSymbolAddress((void**)&tw2h, g_tw2h);
    cudaGetSymbolAddress((void**)&tw2l, g_tw2l);

    cudaFuncSetAttribute(expert_kernel,
                         cudaFuncAttributeMaxDynamicSharedMemorySize, EK_SMEM);
    cudaFuncSetAttribute(task_kernel,
                         cudaFuncAttributeMaxDynamicSharedMemorySize, TK_SMEM);

    const dim3 blk(256);
    const int rowTiles = B_ROWS / 128;   // 64

    // packing
    {
        size_t nx = (size_t)E1_NC * B_ROWS * PK_COLS;
        pack_x_kernel<<<(unsigned)((nx + 255) / 256), 256>>>(x, xph, xpl);
        size_t nw = (size_t)M_EXP * E1_NC * 128 * PK_COLS;
        pack_w_kernel<<<(unsigned)((nw + 255) / 256), 256>>>(eW1, wph, wpl);
        size_t n2 = (size_t)M_EXP * 4 * 96 * PK_COLS;
        pack_w2_kernel<<<(unsigned)((n2 + 255) / 256), 256>>>(
            eW2, M_EXP, 120, 84, w2h, w2l);
        size_t n3 = (size_t)N_TASK * 4 * 96 * PK_COLS;
        pack_w2_kernel<<<(unsigned)((n3 + 255) / 256), 256>>>(
            tW2, N_TASK, 120, 84, tw2h, tw2l);
    }

    // E1+E2+E3 -> EO
    expert_kernel<<<dim3(M_EXP, rowTiles), blk, EK_SMEM>>>(
        xph, xpl, wph, wpl, eb1, w2h, w2l, eb2, eW3, eb3, EO);

    // gate+T1+T2+T3 -> out
    task_kernel<<<dim3(N_TASK, rowTiles), blk, TK_SMEM>>>(
        EO, gw, gm, tW1, tb1, tw2h, tw2l, tb2, tW3, tb3, out);

    // logits_loss -> out tail
    logits_kernel<<<1, 128>>>(gl, out + (long long)N_TASK * B_ROWS * T_OUT);
}

// round 9
// speedup vs baseline: 1.2016x; 1.2016x over previous
#include <cuda_runtime.h>
#include <cuda_bf16.h>
#include <cstdint>
#include <math.h>

// ---------------------------------------------------------------------------
// Problem constants
// ---------------------------------------------------------------------------
#define B_ROWS   8192
#define M_EXP    10
#define N_TASK   100
#define F_CONN   10
#define T_OUT    10
#define K_IN     4096
#define H1_DIM   120

#define E1_BK    32
#define E1_NC    (K_IN / E1_BK)     // 128 chunks
#define PK_COLS  40                 // 32 data bf16 + 8 pad -> 80B rows

// ---------------------------------------------------------------------------
// Scratch (device globals)
// ---------------------------------------------------------------------------
__device__ float g_EO[(size_t)M_EXP * B_ROWS * 10];

__device__ __nv_bfloat16 g_xph[(size_t)E1_NC * B_ROWS * PK_COLS];
__device__ __nv_bfloat16 g_xpl[(size_t)E1_NC * B_ROWS * PK_COLS];
__device__ __nv_bfloat16 g_wph[(size_t)M_EXP * E1_NC * 128 * PK_COLS];
__device__ __nv_bfloat16 g_wpl[(size_t)M_EXP * E1_NC * 128 * PK_COLS];

// packed W2: [batch][chunk 4][96][40]  (hi, lo); per-chunk block = 3840 elems
__device__ __nv_bfloat16 g_w2h[(size_t)M_EXP * 4 * 96 * PK_COLS];
__device__ __nv_bfloat16 g_w2l[(size_t)M_EXP * 4 * 96 * PK_COLS];
__device__ __nv_bfloat16 g_tw2h[(size_t)N_TASK * 4 * 96 * PK_COLS];
__device__ __nv_bfloat16 g_tw2l[(size_t)N_TASK * 4 * 96 * PK_COLS];

// ---------------------------------------------------------------------------
// f32x2 helpers
// ---------------------------------------------------------------------------
__device__ __forceinline__ void fma2(unsigned long long& d,
                                     unsigned long long a,
                                     unsigned long long b) {
    asm("fma.rn.f32x2 %0, %1, %2, %0;" : "+l"(d) : "l"(a), "l"(b));
}
__device__ __forceinline__ unsigned long long dup2(float x) {
    unsigned long long r;
    unsigned int xi = __float_as_uint(x);
    asm("mov.b64 %0, {%1, %1};" : "=l"(r) : "r"(xi));
    return r;
}
__device__ __forceinline__ unsigned long long pack2(float lo, float hi) {
    unsigned long long r;
    asm("mov.b64 %0, {%1, %2};" : "=l"(r)
        : "r"(__float_as_uint(lo)), "r"(__float_as_uint(hi)));
    return r;
}
__device__ __forceinline__ void unpack2(unsigned long long v, float& lo, float& hi) {
    unsigned int a, b;
    asm("mov.b64 {%0, %1}, %2;" : "=r"(a), "=r"(b) : "l"(v));
    lo = __uint_as_float(a);
    hi = __uint_as_float(b);
}

// ---------------------------------------------------------------------------
// PTX helpers (<= sm_90 baseline; legal at virtual arch compute_103)
// ---------------------------------------------------------------------------
__device__ __forceinline__ uint32_t smem_u32(const void* p) {
    uint32_t a;
    asm("{ .reg .u64 t; cvta.to.shared.u64 t, %1; cvt.u32.u64 %0, t; }"
        : "=r"(a) : "l"(p));
    return a;
}
__device__ __forceinline__ void mbar_init(uint32_t mb, uint32_t cnt) {
    asm volatile("mbarrier.init.shared.b64 [%0], %1;" :: "r"(mb), "r"(cnt) : "memory");
}
__device__ __forceinline__ void mbar_expect_tx(uint32_t mb, uint32_t bytes) {
    asm volatile("mbarrier.arrive.expect_tx.shared.b64 _, [%0], %1;"
                 :: "r"(mb), "r"(bytes) : "memory");
}
__device__ __forceinline__ void mbar_wait(uint32_t mb, uint32_t parity) {
    asm volatile("{\n\t.reg .pred P;\n"
                 "W%=:\n\t"
                 "mbarrier.try_wait.parity.acquire.cta.shared::cta.b64 P, [%0], %1, 0x989680;\n\t"
                 "@P bra D%=;\n\t"
                 "bra W%=;\n"
                 "D%=:\n\t}"
                 :: "r"(mb), "r"(parity) : "memory");
}
__device__ __forceinline__ void bulk_g2s(uint32_t dst, const void* src,
                                         uint32_t bytes, uint32_t mb) {
    asm volatile("cp.async.bulk.shared::cta.global.mbarrier::complete_tx::bytes "
                 "[%0], [%1], %2, [%3];"
                 :: "r"(dst), "l"(src), "r"(bytes), "r"(mb) : "memory");
}
__device__ __forceinline__ void ldsm_x4(uint32_t& r0, uint32_t& r1,
                                        uint32_t& r2, uint32_t& r3, uint32_t a) {
    asm volatile("ldmatrix.sync.aligned.m8n8.x4.shared.b16 {%0,%1,%2,%3}, [%4];"
                 : "=r"(r0), "=r"(r1), "=r"(r2), "=r"(r3) : "r"(a));
}
__device__ __forceinline__ void mma_bf16(float& c0, float& c1, float& c2, float& c3,
                                         uint32_t a0, uint32_t a1, uint32_t a2, uint32_t a3,
                                         uint32_t b0, uint32_t b1) {
    asm volatile("mma.sync.aligned.m16n8k16.row.col.f32.bf16.bf16.f32 "
                 "{%0,%1,%2,%3},{%4,%5,%6,%7},{%8,%9},{%0,%1,%2,%3};"
                 : "+f"(c0), "+f"(c1), "+f"(c2), "+f"(c3)
                 : "r"(a0), "r"(a1), "r"(a2), "r"(a3), "r"(b0), "r"(b1));
}

// ---------------------------------------------------------------------------
// Packing kernels
// ---------------------------------------------------------------------------
__global__ void pack_x_kernel(const float* __restrict__ x,
                              __nv_bfloat16* __restrict__ xph,
                              __nv_bfloat16* __restrict__ xpl)
{
    size_t i = (size_t)blockIdx.x * blockDim.x + threadIdx.x;
    const size_t total = (size_t)E1_NC * B_ROWS * PK_COLS;
    if (i >= total) return;
    int col = (int)(i % PK_COLS);
    int row = (int)((i / PK_COLS) % B_ROWS);
    int c   = (int)(i / ((size_t)PK_COLS * B_ROWS));
    float v = 0.f;
    if (col < E1_BK) v = x[(size_t)row * K_IN + c * E1_BK + col];
    __nv_bfloat16 h = __float2bfloat16(v);
    xph[i] = h;
    xpl[i] = __float2bfloat16(v - __bfloat162float(h));
}

__global__ void pack_w_kernel(const float* __restrict__ w,
                              __nv_bfloat16* __restrict__ wph,
                              __nv_bfloat16* __restrict__ wpl)
{
    size_t i = (size_t)blockIdx.x * blockDim.x + threadIdx.x;
    const size_t total = (size_t)M_EXP * E1_NC * 128 * PK_COLS;
    if (i >= total) return;
    int col = (int)(i % PK_COLS);
    int n   = (int)((i / PK_COLS) % 128);
    int c   = (int)((i / ((size_t)PK_COLS * 128)) % E1_NC);
    int m   = (int)(i / ((size_t)PK_COLS * 128 * E1_NC));
    float v = 0.f;
    if (col < E1_BK && n < H1_DIM)
        v = w[((size_t)m * K_IN + c * E1_BK + col) * H1_DIM + n];
    __nv_bfloat16 h = __float2bfloat16(v);
    wph[i] = h;
    wpl[i] = __float2bfloat16(v - __bfloat162float(h));
}

__global__ void pack_w2_kernel(const float* __restrict__ w, int batchN,
                               int Kreal, int Nreal,
                               __nv_bfloat16* __restrict__ wh,
                               __nv_bfloat16* __restrict__ wl)
{
    size_t i = (size_t)blockIdx.x * blockDim.x + threadIdx.x;
    size_t total = (size_t)batchN * 4 * 96 * PK_COLS;
    if (i >= total) return;
    int col = (int)(i % PK_COLS);
    int n   = (int)((i / PK_COLS) % 96);
    int c   = (int)((i / (PK_COLS * 96)) % 4);
    int b   = (int)(i / ((size_t)PK_COLS * 96 * 4));
    int k   = c * 32 + col;
    float v = (col < 32 && k < Kreal && n < Nreal)
              ? w[((size_t)b * Kreal + k) * Nreal + n] : 0.f;
    __nv_bfloat16 h = __float2bfloat16(v);
    wh[i] = h;
    wl[i] = __float2bfloat16(v - __bfloat162float(h));
}

// ---------------------------------------------------------------------------
// expert_kernel: E1 (2-stage bulk pipeline) + E2 (streamed-B HMMA) + E3 epi
// smem 100,704 B -> 2 CTAs/SM.   grid = (M_EXP, 64), 256 threads.
// ---------------------------------------------------------------------------
#define RS          80
#define STG_SZ      40960         // per E1 stage: XA_H|XA_L|XB_H|XB_L @ 10240
#define XA_H        0
#define XA_L        10240
#define XB_H        20480
#define XB_L        30720
#define EB_H        81920         // E2 B hi (7680)
#define EB_L        89600         // E2 B lo (7680)
#define EW3S        97280         // 3360
#define EMB         100640        // 3 mbarriers (24B)
#define EK_SMEM     100704
#define MSTR        90            // mids row stride (floats); mids overlay @0

__global__ __launch_bounds__(256, 2)
void expert_kernel(const __nv_bfloat16* __restrict__ xph,
                   const __nv_bfloat16* __restrict__ xpl,
                   const __nv_bfloat16* __restrict__ wph,
                   const __nv_bfloat16* __restrict__ wpl,
                   const float* __restrict__ eb1,
                   const __nv_bfloat16* __restrict__ w2h,
                   const __nv_bfloat16* __restrict__ w2l,
                   const float* __restrict__ eb2,
                   const float* __restrict__ eW3,
                   const float* __restrict__ eb3,
                   float* __restrict__ EO)
{
    extern __shared__ char smem[];
    const uint32_t sb = smem_u32(smem);
    const int t    = threadIdx.x;
    const int lane = t & 31;
    const int wid  = t >> 5;
    const int wm   = wid >> 1;
    const int wn   = wid & 1;

    const int m     = blockIdx.x;
    const int tileY = blockIdx.y;
    const int r0    = tileY * 128;

    const uint32_t mb = sb + EMB;   // +0,+8: E1 stages; +16: E2 B

    if (t == 0) {
        mbar_init(mb + 0, 1);
        mbar_init(mb + 8, 1);
        mbar_init(mb + 16, 1);
    }
    __syncthreads();

    auto issue_e1 = [&](int c, int s) {
        mbar_expect_tx(mb + 8 * s, 4 * 10240);
        const uint32_t stg = sb + s * STG_SZ;
        const size_t aoff = ((size_t)c * B_ROWS + (size_t)tileY * 128) * PK_COLS;
        const size_t boff = ((size_t)m * E1_NC + c) * 128 * PK_COLS;
        bulk_g2s(stg + XA_H, xph + aoff, 10240, mb + 8 * s);
        bulk_g2s(stg + XA_L, xpl + aoff, 10240, mb + 8 * s);
        bulk_g2s(stg + XB_H, wph + boff, 10240, mb + 8 * s);
        bulk_g2s(stg + XB_L, wpl + boff, 10240, mb + 8 * s);
    };

    if (t == 0) {
        // E2 B chunk0 early: overlaps all of E1
        mbar_expect_tx(mb + 16, 2 * 7680);
        bulk_g2s(sb + EB_H, w2h + (size_t)m * 4 * 3840, 7680, mb + 16);
        bulk_g2s(sb + EB_L, w2l + (size_t)m * 4 * 3840, 7680, mb + 16);
        issue_e1(0, 0);
    }

    // ---------------- E1 ----------------
    float acc[2][8][4];
    #pragma unroll
    for (int i = 0; i < 2; i++)
        #pragma unroll
        for (int j = 0; j < 8; j++)
            #pragma unroll
            for (int q = 0; q < 4; q++)
                acc[i][j][q] = 0.f;

    const uint32_t a_base = (uint32_t)((wm * 32 + (lane & 15)) * RS + (lane >> 4) * 16);
    const uint32_t b_base = (uint32_t)((wn * 64 + (lane & 15)) * RS + (lane >> 4) * 16);

    uint32_t ph[2] = {0u, 0u};

    for (int c = 0; c < E1_NC; c++) {
        const int s = c & 1;
        if (c + 1 < E1_NC && t == 0) issue_e1(c + 1, s ^ 1);
        mbar_wait(mb + 8 * s, ph[s]);
        ph[s] ^= 1u;

        const uint32_t stg = sb + s * STG_SZ;
        #pragma unroll
        for (int ks = 0; ks < 2; ks++) {
            const uint32_t ko = ks * 32;
            uint32_t ah[2][4], al[2][4];
            #pragma unroll
            for (int mt = 0; mt < 2; mt++) {
                uint32_t ad = stg + a_base + mt * (16 * RS) + ko;
                ldsm_x4(ah[mt][0], ah[mt][1], ah[mt][2], ah[mt][3], ad + XA_H);
                ldsm_x4(al[mt][0], al[mt][1], al[mt][2], al[mt][3], ad + XA_L);
            }
            uint32_t bh[4][4], bl[4][4];
            #pragma unroll
            for (int g = 0; g < 4; g++) {
                uint32_t bd = stg + b_base + g * (16 * RS) + ko;
                ldsm_x4(bh[g][0], bh[g][1], bh[g][2], bh[g][3], bd + XB_H);
                ldsm_x4(bl[g][0], bl[g][1], bl[g][2], bl[g][3], bd + XB_L);
            }
            #pragma unroll
            for (int mt = 0; mt < 2; mt++) {
                #pragma unroll
                for (int nt = 0; nt < 8; nt++) {
                    const int g = nt >> 1, p = (nt & 1);
                    float* cc = acc[mt][nt];
                    mma_bf16(cc[0], cc[1], cc[2], cc[3],
                             ah[mt][0], ah[mt][1], ah[mt][2], ah[mt][3],
                             bh[g][p], bh[g][p + 2]);
                    mma_bf16(cc[0], cc[1], cc[2], cc[3],
                             ah[mt][0], ah[mt][1], ah[mt][2], ah[mt][3],
                             bl[g][p], bl[g][p + 2]);
                    mma_bf16(cc[0], cc[1], cc[2], cc[3],
                             al[mt][0], al[mt][1], al[mt][2], al[mt][3],
                             bh[g][p], bh[g][p + 2]);
                }
            }
        }
        __syncthreads();
    }

    // ---------------- H1 tile -> smem (relu+bias, split hi/lo) ----------------
    // E2 A layout: Ah chunk c at [c*10240, ...), Al at [40960 + c*10240, ...)
    {
        const float* bias = eb1 + (size_t)m * H1_DIM;
        const int rl = wm * 32 + (lane >> 2);
        const int cb = wn * 64 + (lane & 3) * 2;
        #pragma unroll
        for (int mt = 0; mt < 2; mt++) {
            #pragma unroll
            for (int half = 0; half < 2; half++) {
                const int r = rl + mt * 16 + half * 8;
                #pragma unroll
                for (int nt = 0; nt < 8; nt++) {
                    const int ccol = cb + nt * 8;
                    if (ccol < H1_DIM) {
                        float v0 = fmaxf(acc[mt][nt][half * 2 + 0] + bias[ccol], 0.f);
                        float v1 = fmaxf(acc[mt][nt][half * 2 + 1] + bias[ccol + 1], 0.f);
                        __nv_bfloat16 h0 = __float2bfloat16(v0);
                        __nv_bfloat16 h1 = __float2bfloat16(v1);
                        __nv_bfloat162 hh; hh.x = h0; hh.y = h1;
                        __nv_bfloat162 ll;
                        ll.x = __float2bfloat16(v0 - __bfloat162float(h0));
                        ll.y = __float2bfloat16(v1 - __bfloat162float(h1));
                        uint32_t off = (ccol >> 5) * 10240 + r * RS + (ccol & 31) * 2;
                        *reinterpret_cast<__nv_bfloat162*>(smem + 0     + off) = hh;
                        *reinterpret_cast<__nv_bfloat162*>(smem + 40960 + off) = ll;
                    }
                }
            }
        }
        if (t < 128) {   // zero A pad: chunk3, k=120..127
            uint32_t off = 3 * 10240 + t * RS + 48;
            *reinterpret_cast<uint4*>(smem + 0     + off) = make_uint4(0u,0u,0u,0u);
            *reinterpret_cast<uint4*>(smem + 40960 + off) = make_uint4(0u,0u,0u,0u);
        }
        float* w3s = reinterpret_cast<float*>(smem + EW3S);
        const float* w3g = eW3 + (size_t)m * (84 * T_OUT);
        for (int i = t; i < 84 * T_OUT; i += 256) w3s[i] = w3g[i];
    }
    __syncthreads();

    // ---------------- E2 MMA (B streamed per chunk) ----------------
    float acc2[2][6][4];
    #pragma unroll
    for (int i = 0; i < 2; i++)
        #pragma unroll
        for (int j = 0; j < 6; j++)
            #pragma unroll
            for (int q = 0; q < 4; q++)
                acc2[i][j][q] = 0.f;

    const uint32_t b2_base = (uint32_t)((wn * 48 + (lane & 15)) * RS + (lane >> 4) * 16);
    uint32_t phb = 0u;
    #pragma unroll
    for (int ch = 0; ch < 4; ch++) {
        mbar_wait(mb + 16, phb);
        phb ^= 1u;
        #pragma unroll
        for (int ks = 0; ks < 2; ks++) {
            const uint32_t ko = ks * 32;
            uint32_t ah[2][4], al[2][4];
            #pragma unroll
            for (int mt = 0; mt < 2; mt++) {
                uint32_t ad = sb + ch * 10240 + a_base + mt * (16 * RS) + ko;
                ldsm_x4(ah[mt][0], ah[mt][1], ah[mt][2], ah[mt][3], ad + 0);
                ldsm_x4(al[mt][0], al[mt][1], al[mt][2], al[mt][3], ad + 40960);
            }
            uint32_t bh[3][4], bl[3][4];
            #pragma unroll
            for (int g = 0; g < 3; g++) {
                uint32_t bd = sb + b2_base + g * (16 * RS) + ko;
                ldsm_x4(bh[g][0], bh[g][1], bh[g][2], bh[g][3], bd + EB_H);
                ldsm_x4(bl[g][0], bl[g][1], bl[g][2], bl[g][3], bd + EB_L);
            }
            #pragma unroll
            for (int mt = 0; mt < 2; mt++) {
                #pragma unroll
                for (int nt = 0; nt < 6; nt++) {
                    const int g = nt >> 1, p = (nt & 1);
                    float* cc = acc2[mt][nt];
                    mma_bf16(cc[0], cc[1], cc[2], cc[3],
                             ah[mt][0], ah[mt][1], ah[mt][2], ah[mt][3],
                             bh[g][p], bh[g][p + 2]);
                    mma_bf16(cc[0], cc[1], cc[2], cc[3],
                             ah[mt][0], ah[mt][1], ah[mt][2], ah[mt][3],
                             bl[g][p], bl[g][p + 2]);
                    mma_bf16(cc[0], cc[1], cc[2], cc[3],
                             al[mt][0], al[mt][1], al[mt][2], al[mt][3],
                             bh[g][p], bh[g][p + 2]);
                }
            }
        }
        __syncthreads();
        if (ch < 3 && t == 0) {
            mbar_expect_tx(mb + 16, 2 * 7680);
            bulk_g2s(sb + EB_H, w2h + ((size_t)m * 4 + ch + 1) * 3840, 7680, mb + 16);
            bulk_g2s(sb + EB_L, w2l + ((size_t)m * 4 + ch + 1) * 3840, 7680, mb + 16);
        }
    }

    // ---------------- E3 epilogue ----------------
    float* mids = reinterpret_cast<float*>(smem);        // overlay A
    float* w3s  = reinterpret_cast<float*>(smem + EW3S);
    {
        const float* b2 = eb2 + (size_t)m * 84;
        const int rl = wm * 32 + (lane >> 2);
        const int cb = wn * 48 + (lane & 3) * 2;
        #pragma unroll
        for (int mt = 0; mt < 2; mt++) {
            #pragma unroll
            for (int half = 0; half < 2; half++) {
                const int r = rl + mt * 16 + half * 8;
                float* row = mids + r * MSTR;
                #pragma unroll
                for (int nt = 0; nt < 6; nt++) {
                    const int ccol = cb + nt * 8;
                    if (ccol < 84) {
                        float2 v;
                        v.x = fmaxf(acc2[mt][nt][half * 2 + 0] + b2[ccol], 0.f);
                        v.y = fmaxf(acc2[mt][nt][half * 2 + 1] + b2[ccol + 1], 0.f);
                        *reinterpret_cast<float2*>(row + ccol) = v;
                    }
                }
            }
        }
    }
    __syncthreads();
    {
        const int r  = t >> 1;
        const int c0 = (t & 1) * 5;
        const float* b3 = eb3 + (size_t)m * T_OUT;
        float a[5];
        #pragma unroll
        for (int j = 0; j < 5; j++) a[j] = b3[c0 + j];
        const float* row = mids + r * MSTR;
        for (int k = 0; k < 84; k++) {
            float tv = row[k];
            #pragma unroll
            for (int j = 0; j < 5; j++)
                a[j] = fmaf(tv, w3s[k * T_OUT + c0 + j], a[j]);
        }
        float* dst = EO + ((size_t)m * B_ROWS + r0 + r) * T_OUT + c0;
        #pragma unroll
        for (int j = 0; j < 5; j++) dst[j] = a[j];
    }
}

// ---------------------------------------------------------------------------
// task_kernel: gate + T1 (FFMA2) + T2 (streamed-B HMMA) + T3 epilogue
// smem 110,592 B -> 2 CTAs/SM.   grid = (N_TASK, 64), 256 threads.
// ---------------------------------------------------------------------------
#define TK_AH      0              // [4][128][40] = 40960
#define TK_AL      40960
#define TB_H       81920          // 7680
#define TB_L       89600          // 7680
#define TK_GS      97280          // 5120
#define TK_W1      102400         // 4800
#define TK_W3      107200         // 3360
#define TK_MB      110560         // 8
#define TK_SMEM    110592

__global__ __launch_bounds__(256, 2)
void task_kernel(const float* __restrict__ EO,
                 const float* __restrict__ gw,
                 const int*   __restrict__ gm,
                 const float* __restrict__ tW1,
                 const float* __restrict__ tb1,
                 const __nv_bfloat16* __restrict__ tw2h,
                 const __nv_bfloat16* __restrict__ tw2l,
                 const float* __restrict__ tb2,
                 const float* __restrict__ tW3,
                 const float* __restrict__ tb3,
                 float* __restrict__ Out)
{
    extern __shared__ char smem[];
    const uint32_t sb = smem_u32(smem);
    const int t    = threadIdx.x;
    const int lane = t & 31;
    const int wid  = t >> 5;
    const int wm   = wid >> 1;
    const int wn   = wid & 1;

    const int n  = blockIdx.x;
    const int r0 = blockIdx.y * 128;

    const uint32_t mb = sb + TK_MB;
    if (t == 0) mbar_init(mb, 1);
    __syncthreads();
    if (t == 0) {   // B chunk0 early: overlaps gate + T1
        mbar_expect_tx(mb, 2 * 7680);
        bulk_g2s(sb + TB_H, tw2h + (size_t)n * 4 * 3840, 7680, mb);
        bulk_g2s(sb + TB_L, tw2l + (size_t)n * 4 * 3840, 7680, mb);
    }

    float* Gs  = reinterpret_cast<float*>(smem + TK_GS);
    float* W1s = reinterpret_cast<float*>(smem + TK_W1);
    float* w3s = reinterpret_cast<float*>(smem + TK_W3);

    float w[M_EXP];
    #pragma unroll
    for (int m = 0; m < M_EXP; m++)
        w[m] = gw[m * N_TASK + n] * (float)gm[m * N_TASK + n];

    for (int i = t; i < 128 * F_CONN; i += 256) {
        float acc = 0.f;
        #pragma unroll
        for (int m = 0; m < M_EXP; m++)
            acc = fmaf(w[m], EO[((size_t)m * B_ROWS + r0) * F_CONN + i], acc);
        Gs[i] = acc;
    }
    for (int i = t; i < F_CONN * 120; i += 256)
        W1s[i] = tW1[(size_t)n * F_CONN * 120 + i];
    for (int i = t; i < 84 * T_OUT; i += 256)
        w3s[i] = tW3[(size_t)n * 84 * T_OUT + i];
    __syncthreads();

    // T1: thread = (row, 60-col half); relu'd hi/lo -> A tile
    {
        const int r  = t >> 1;
        const int h0 = (t & 1) * 60;
        float g[F_CONN];
        #pragma unroll
        for (int f = 0; f < F_CONN; f++) g[f] = Gs[r * F_CONN + f];

        unsigned long long a2[30];
        const float* b1 = tb1 + (size_t)n * 120 + h0;
        #pragma unroll
        for (int j = 0; j < 30; j++) a2[j] = pack2(b1[2 * j], b1[2 * j + 1]);
        #pragma unroll
        for (int f = 0; f < F_CONN; f++) {
            unsigned long long gv = dup2(g[f]);
            const unsigned long long* wrow =
                reinterpret_cast<const unsigned long long*>(W1s + f * 120 + h0);
            #pragma unroll
            for (int j = 0; j < 30; j++) fma2(a2[j], gv, wrow[j]);
        }
        #pragma unroll
        for (int j = 0; j < 30; j++) {
            float v0, v1;
            unpack2(a2[j], v0, v1);
            v0 = fmaxf(v0, 0.f);
            v1 = fmaxf(v1, 0.f);
            __nv_bfloat16 h0b = __float2bfloat16(v0);
            __nv_bfloat16 h1b = __float2bfloat16(v1);
            __nv_bfloat162 hh; hh.x = h0b; hh.y = h1b;
            __nv_bfloat162 ll;
            ll.x = __float2bfloat16(v0 - __bfloat162float(h0b));
            ll.y = __float2bfloat16(v1 - __bfloat162float(h1b));
            const int c = h0 + 2 * j;
            uint32_t off = (c >> 5) * 10240 + r * RS + (c & 31) * 2;
            *reinterpret_cast<__nv_bfloat162*>(smem + TK_AH + off) = hh;
            *reinterpret_cast<__nv_bfloat162*>(smem + TK_AL + off) = ll;
        }
        if (t & 1) {   // zero A pad: chunk3, k=120..127
            uint32_t off = 3 * 10240 + r * RS + 48;
            *reinterpret_cast<uint4*>(smem + TK_AH + off) = make_uint4(0u,0u,0u,0u);
            *reinterpret_cast<uint4*>(smem + TK_AL + off) = make_uint4(0u,0u,0u,0u);
        }
    }
    __syncthreads();

    // T2 MMA (B streamed per chunk)
    float acc2[2][6][4];
    #pragma unroll
    for (int i = 0; i < 2; i++)
        #pragma unroll
        for (int j = 0; j < 6; j++)
            #pragma unroll
            for (int q = 0; q < 4; q++)
                acc2[i][j][q] = 0.f;

    const uint32_t a_base  = (uint32_t)((wm * 32 + (lane & 15)) * RS + (lane >> 4) * 16);
    const uint32_t b2_base = (uint32_t)((wn * 48 + (lane & 15)) * RS + (lane >> 4) * 16);
    uint32_t phb = 0u;
    #pragma unroll
    for (int ch = 0; ch < 4; ch++) {
        mbar_wait(mb, phb);
        phb ^= 1u;
        #pragma unroll
        for (int ks = 0; ks < 2; ks++) {
            const uint32_t ko = ks * 32;
            uint32_t ah[2][4], al[2][4];
            #pragma unroll
            for (int mt = 0; mt < 2; mt++) {
                uint32_t ad = sb + ch * 10240 + a_base + mt * (16 * RS) + ko;
                ldsm_x4(ah[mt][0], ah[mt][1], ah[mt][2], ah[mt][3], ad + TK_AH);
                ldsm_x4(al[mt][0], al[mt][1], al[mt][2], al[mt][3], ad + TK_AL);
            }
            uint32_t bh[3][4], bl[3][4];
            #pragma unroll
            for (int g = 0; g < 3; g++) {
                uint32_t bd = sb + b2_base + g * (16 * RS) + ko;
                ldsm_x4(bh[g][0], bh[g][1], bh[g][2], bh[g][3], bd + TB_H);
                ldsm_x4(bl[g][0], bl[g][1], bl[g][2], bl[g][3], bd + TB_L);
            }
            #pragma unroll
            for (int mt = 0; mt < 2; mt++) {
                #pragma unroll
                for (int nt = 0; nt < 6; nt++) {
                    const int g = nt >> 1, p = (nt & 1);
                    float* cc = acc2[mt][nt];
                    mma_bf16(cc[0], cc[1], cc[2], cc[3],
                             ah[mt][0], ah[mt][1], ah[mt][2], ah[mt][3],
                             bh[g][p], bh[g][p + 2]);
                    mma_bf16(cc[0], cc[1], cc[2], cc[3],
                             ah[mt][0], ah[mt][1], ah[mt][2], ah[mt][3],
                             bl[g][p], bl[g][p + 2]);
                    mma_bf16(cc[0], cc[1], cc[2], cc[3],
                             al[mt][0], al[mt][1], al[mt][2], al[mt][3],
                             bh[g][p], bh[g][p + 2]);
                }
            }
        }
        __syncthreads();
        if (ch < 3 && t == 0) {
            mbar_expect_tx(mb, 2 * 7680);
            bulk_g2s(sb + TB_H, tw2h + ((size_t)n * 4 + ch + 1) * 3840, 7680, mb);
            bulk_g2s(sb + TB_L, tw2l + ((size_t)n * 4 + ch + 1) * 3840, 7680, mb);
        }
    }

    // T3 epilogue
    float* mids = reinterpret_cast<float*>(smem);       // overlay A
    {
        const float* b2 = tb2 + (size_t)n * 84;
        const int rl = wm * 32 + (lane >> 2);
        const int cb = wn * 48 + (lane & 3) * 2;
        #pragma unroll
        for (int mt = 0; mt < 2; mt++) {
            #pragma unroll
            for (int half = 0; half < 2; half++) {
                const int r = rl + mt * 16 + half * 8;
                float* row = mids + r * MSTR;
                #pragma unroll
                for (int nt = 0; nt < 6; nt++) {
                    const int ccol = cb + nt * 8;
                    if (ccol < 84) {
                        float2 v;
                        v.x = fmaxf(acc2[mt][nt][half * 2 + 0] + b2[ccol], 0.f);
                        v.y = fmaxf(acc2[mt][nt][half * 2 + 1] + b2[ccol + 1], 0.f);
                        *reinterpret_cast<float2*>(row + ccol) = v;
                    }
                }
            }
        }
    }
    __syncthreads();
    {
        const int r  = t >> 1;
        const int c0 = (t & 1) * 5;
        const float* b3 = tb3 + (size_t)n * T_OUT;
        float a[5];
        #pragma unroll
        for (int j = 0; j < 5; j++) a[j] = b3[c0 + j];
        const float* row = mids + r * MSTR;
        for (int k = 0; k < 84; k++) {
            float tv = row[k];
            #pragma unroll
            for (int j = 0; j < 5; j++)
                a[j] = fmaf(tv, w3s[k * T_OUT + c0 + j], a[j]);
        }
        float* dst = Out + ((size_t)n * B_ROWS + r0 + r) * T_OUT + c0;
        #pragma unroll
        for (int j = 0; j < 5; j++) dst[j] = a[j];
    }
}

// ---------------------------------------------------------------------------
// logits_loss[n] = sum_m log_sigmoid(gate_logits[m][n])
// ---------------------------------------------------------------------------
__global__ void logits_kernel(const float* __restrict__ gl, float* __restrict__ out)
{
    int n = blockIdx.x * blockDim.x + threadIdx.x;
    if (n >= N_TASK) return;
    float acc = 0.f;
    #pragma unroll
    for (int m = 0; m < M_EXP; m++) {
        float v = gl[m * N_TASK + n];
        float ls = (v > 0.f) ? (-log1pf(expf(-v))) : (v - log1pf(expf(v)));
        acc += ls;
    }
    out[n] = acc;
}

// ---------------------------------------------------------------------------
// kernel_launch
// ---------------------------------------------------------------------------
extern "C" void kernel_launch(void* const* d_in, const int* in_sizes, int n_in,
                              void* d_out, int out_size)
{
    const float* x   = (const float*)d_in[0];
    const float* eW1 = (const float*)d_in[2];
    const float* eb1 = (const float*)d_in[3];
    const float* eW2 = (const float*)d_in[4];
    const float* eb2 = (const float*)d_in[5];
    const float* eW3 = (const float*)d_in[6];
    const float* eb3 = (const float*)d_in[7];
    const float* gw  = (const float*)d_in[8];
    const float* gl  = (const float*)d_in[9];
    const int*   gm  = (const int*)  d_in[10];
    const float* tW1 = (const float*)d_in[11];
    const float* tb1 = (const float*)d_in[12];
    const float* tW2 = (const float*)d_in[13];
    const float* tb2 = (const float*)d_in[14];
    const float* tW3 = (const float*)d_in[15];
    const float* tb3 = (const float*)d_in[16];
    float* out = (float*)d_out;

    float *EO;
    __nv_bfloat16 *xph, *xpl, *wph, *wpl, *w2h, *w2l, *tw2h, *tw2l;
    cudaGetSymbolAddress((void**)&EO,  g_EO);
    cudaGetSymbolAddress((void**)&xph, g_xph);
    cudaGetSymbolAddress((void**)&xpl, g_xpl);
    cudaGetSymbolAddress((void**)&wph, g_wph);
    cudaGetSymbolAddress((void**)&wpl, g_wpl);
    cudaGetSymbolAddress((void**)&w2h, g_w2h);
    cudaGetSymbolAddress((void**)&w2l, g_w2l);
    cudaGetSymbolAddress((void**)&tw2h, g_tw2h);
    cudaGetSymbolAddress((void**)&tw2l, g_tw2l);

    cudaFuncSetAttribute(expert_kernel,
                         cudaFuncAttributeMaxDynamicSharedMemorySize, EK_SMEM);
    cudaFuncSetAttribute(task_kernel,
                         cudaFuncAttributeMaxDynamicSharedMemorySize, TK_SMEM);

    const dim3 blk(256);
    const int rowTiles = B_ROWS / 128;   // 64

    {
        size_t nx = (size_t)E1_NC * B_ROWS * PK_COLS;
        pack_x_kernel<<<(unsigned)((nx + 255) / 256), 256>>>(x, xph, xpl);
        size_t nw = (size_t)M_EXP * E1_NC * 128 * PK_COLS;
        pack_w_kernel<<<(unsigned)((nw + 255) / 256), 256>>>(eW1, wph, wpl);
        size_t n2 = (size_t)M_EXP * 4 * 96 * PK_COLS;
        pack_w2_kernel<<<(unsigned)((n2 + 255) / 256), 256>>>(
            eW2, M_EXP, 120, 84, w2h, w2l);
        size_t n3 = (size_t)N_TASK * 4 * 96 * PK_COLS;
        pack_w2_kernel<<<(unsigned)((n3 + 255) / 256), 256>>>(
            tW2, N_TASK, 120, 84, tw2h, tw2l);
    }

    expert_kernel<<<dim3(M_EXP, rowTiles), blk, EK_SMEM>>>(
        xph, xpl, wph, wpl, eb1, w2h, w2l, eb2, eW3, eb3, EO);

    task_kernel<<<dim3(N_TASK, rowTiles), blk, TK_SMEM>>>(
        EO, gw, gm, tW1, tb1, tw2h, tw2l, tb2, tW3, tb3, out);

    logits_kernel<<<1, 128>>>(gl, out + (long long)N_TASK * B_ROWS * T_OUT);
}